// round 4
// baseline (speedup 1.0000x reference)
#include <cuda_runtime.h>
#include <cuda_bf16.h>
#include <math.h>

#define NEG_INF (-1e30f)
#define NB 16
#define LC 2048
#define LQ 512
#define DD 512
#define D4 2048

__device__ float g_Cp[NB * LC * DD];
__device__ float g_Qp[NB * LQ * DD];
__device__ float g_S [NB * LC * LQ];
__device__ float g_A [NB * LC * DD];
__device__ float g_Qt[NB * DD * LQ];
__device__ int   g_idx[NB * LC];
__device__ int   g_cnt[NB];

// ---------------------------------------------------------------------------
__device__ __forceinline__ unsigned pk(float a, float b) {
    __nv_bfloat162 h = __floats2bfloat162_rn(a, b);
    return *reinterpret_cast<unsigned*>(&h);
}

__device__ __forceinline__ void mma_bf16(float* d, const unsigned* a, const unsigned* b) {
    asm volatile(
        "mma.sync.aligned.m16n8k16.row.col.f32.bf16.bf16.f32 "
        "{%0,%1,%2,%3}, {%4,%5,%6,%7}, {%8,%9}, {%0,%1,%2,%3};\n"
        : "+f"(d[0]), "+f"(d[1]), "+f"(d[2]), "+f"(d[3])
        : "r"(a[0]), "r"(a[1]), "r"(a[2]), "r"(a[3]), "r"(b[0]), "r"(b[1]));
}

__device__ __forceinline__ void ldsm4(unsigned* r, unsigned addr) {
    asm volatile("ldmatrix.sync.aligned.m8n8.x4.shared.b16 {%0,%1,%2,%3}, [%4];"
                 : "=r"(r[0]), "=r"(r[1]), "=r"(r[2]), "=r"(r[3]) : "r"(addr));
}

__device__ __forceinline__ unsigned sptr(const void* p) {
    return (unsigned)__cvta_generic_to_shared(p);
}

// Load 16 consecutive fp32 -> 8 packed bf16x2
__device__ __forceinline__ void loadA16(unsigned* ra, const float* p) {
    float4 f0 = *(const float4*)(p);
    float4 f1 = *(const float4*)(p + 4);
    float4 f2 = *(const float4*)(p + 8);
    float4 f3 = *(const float4*)(p + 12);
    ra[0] = pk(f0.x, f0.y); ra[1] = pk(f0.z, f0.w);
    ra[2] = pk(f1.x, f1.y); ra[3] = pk(f1.z, f1.w);
    ra[4] = pk(f2.x, f2.y); ra[5] = pk(f2.z, f2.w);
    ra[6] = pk(f3.x, f3.y); ra[7] = pk(f3.z, f3.w);
}

// Load 8 consecutive fp32 -> 4 packed bf16x2
__device__ __forceinline__ void loadB8(unsigned* rb, const float* p) {
    float4 g0 = *(const float4*)(p);
    float4 g1 = *(const float4*)(p + 4);
    rb[0] = pk(g0.x, g0.y); rb[1] = pk(g0.z, g0.w);
    rb[2] = pk(g1.x, g1.y); rb[3] = pk(g1.z, g1.w);
}

// SMEM layout: row-major bf16 tiles, row stride 5 x 16B chunks (80B).
// Row r, chunk c (8 bf16) at uint4 index r*5 + c.  5 odd => (5r+c) mod 8
// permutes -> ldmatrix (8 rows, fixed chunk) conflict-free.
#define AROWS 128
#define BROWS 64
#define ACH   (AROWS * 5)
#define BCH   (BROWS * 5)

// ---------------------------------------------------------------------------
__global__ void compact_kernel(const int* __restrict__ Cmask) {
    __shared__ int toff[257];
    int b = blockIdx.x;
    int t = threadIdx.x;
    int flags[8];
    int s = 0;
#pragma unroll
    for (int i = 0; i < 8; i++) {
        flags[i] = (Cmask[b * LC + t * 8 + i] != 0) ? 1 : 0;
        s += flags[i];
    }
    toff[t + 1] = s;
    __syncthreads();
    if (t == 0) {
        toff[0] = 0;
        for (int i = 1; i <= 256; i++) toff[i] += toff[i - 1];
        g_cnt[b] = toff[256];
    }
    __syncthreads();
    int pos = toff[t];
#pragma unroll
    for (int i = 0; i < 8; i++) {
        if (flags[i]) g_idx[b * LC + (pos++)] = t * 8 + i;
    }
}

__global__ void fill_masked_kernel(const int* __restrict__ Cmask,
                                   float* __restrict__ out) {
    int c = blockIdx.y;
    int b = blockIdx.z;
    if (Cmask[b * LC + c] != 0) return;
    float4* p = (float4*)(out + ((size_t)(b * LC + c)) * D4);
    float4 v = make_float4(NEG_INF, NEG_INF, NEG_INF, NEG_INF);
    int t = threadIdx.x;
    p[t] = v; p[t + 128] = v; p[t + 256] = v; p[t + 384] = v;
}

__global__ void transpose_q_kernel(const float* __restrict__ Q) {
    __shared__ float t[32][33];
    int b = blockIdx.z;
    int d0 = blockIdx.x * 32, q0 = blockIdx.y * 32;
    int tx = threadIdx.x, ty = threadIdx.y;
#pragma unroll
    for (int i = 0; i < 4; i++)
        t[ty + i * 8][tx] = Q[((size_t)b * LQ + q0 + ty + i * 8) * DD + d0 + tx];
    __syncthreads();
#pragma unroll
    for (int i = 0; i < 4; i++)
        g_Qt[((size_t)b * DD + d0 + ty + i * 8) * LQ + q0 + tx] = t[tx][ty + i * 8];
}

// ---------------------------------------------------------------------------
// Generic NT bf16-MMA GEMM with ldmatrix smem path.
// BM=128 BN=64 BK=32, 256 threads (8 warps: 4 m-tiles x 2 n-tiles of 32x32).
// ---------------------------------------------------------------------------
__global__ __launch_bounds__(256, 2)
void gemm_nt_mma(const float* __restrict__ A, int lda, int Arows_per_b,
                 const float* __restrict__ B, int ldb, int Brows_per_b,
                 float* __restrict__ Y, int ldy,
                 const float* __restrict__ bias,
                 int K, int Mfull, int use_cnt, int gather, int mode) {
    int b  = blockIdx.z;
    int m0 = blockIdx.y * 128;
    int n0 = blockIdx.x * 64;
    int M  = use_cnt ? g_cnt[b] : Mfull;
    if (m0 >= M) return;

    __shared__ __align__(16) uint4 sA[2][ACH];
    __shared__ __align__(16) uint4 sB[2][BCH];

    int tid = threadIdx.x;
    // producer mapping: conflict-free STS.128
    int am  = tid & 127, aks = tid >> 7;      // A: row, k-half (16 wide)
    int bn  = tid & 63,  bkc = tid >> 6;      // B: row, chunk (8 wide)

    int j = min(m0 + am, M - 1);
    int s = gather ? g_idx[b * LC + j] : j;
    const float* Arow = A + ((size_t)b * Arows_per_b + s) * lda + aks * 16;
    const float* Brow = B + ((size_t)b * Brows_per_b + n0 + bn) * ldb + bkc * 8;

    int lane = tid & 31, w = tid >> 5;
    int wm = w >> 1, wn = w & 1;

    // consumer lane offsets (in uint4 units)
    int a_off = (wm * 32 + (lane & 15)) * 5 + (lane >> 4);
    int b_off = (wn * 32 + ((lane >> 4) << 3) + (lane & 7)) * 5 + ((lane >> 3) & 1);

    float acc[2][4][4];
#pragma unroll
    for (int mi = 0; mi < 2; mi++)
#pragma unroll
        for (int ni = 0; ni < 4; ni++)
#pragma unroll
            for (int r = 0; r < 4; r++) acc[mi][ni][r] = 0.f;

    unsigned ra[8], rb[4];
    loadA16(ra, Arow);
    loadB8(rb, Brow);

    const int KIT = K / 32;
    for (int it = 0; it < KIT; it++) {
        int buf = it & 1;
        sA[buf][am * 5 + aks * 2 + 0] = make_uint4(ra[0], ra[1], ra[2], ra[3]);
        sA[buf][am * 5 + aks * 2 + 1] = make_uint4(ra[4], ra[5], ra[6], ra[7]);
        sB[buf][bn * 5 + bkc] = make_uint4(rb[0], rb[1], rb[2], rb[3]);
        __syncthreads();
        if (it + 1 < KIT) {
            loadA16(ra, Arow + (it + 1) * 32);
            loadB8(rb, Brow + (it + 1) * 32);
        }
        unsigned abase = sptr(&sA[buf][0]);
        unsigned bbase = sptr(&sB[buf][0]);
#pragma unroll
        for (int ks = 0; ks < 2; ks++) {
            unsigned av[2][4], bv[2][4];
#pragma unroll
            for (int mi = 0; mi < 2; mi++)
                ldsm4(av[mi], abase + (unsigned)(a_off + mi * 16 * 5 + ks * 2) * 16);
#pragma unroll
            for (int np = 0; np < 2; np++)
                ldsm4(bv[np], bbase + (unsigned)(b_off + np * 16 * 5 + ks * 2) * 16);
#pragma unroll
            for (int mi = 0; mi < 2; mi++)
#pragma unroll
                for (int ni = 0; ni < 4; ni++) {
                    unsigned bb[2] = { bv[ni >> 1][(ni & 1) * 2 + 0],
                                       bv[ni >> 1][(ni & 1) * 2 + 1] };
                    mma_bf16(acc[mi][ni], av[mi], bb);
                }
        }
        __syncthreads();
    }

    int gid = lane >> 2, tig = lane & 3;
#pragma unroll
    for (int mi = 0; mi < 2; mi++) {
#pragma unroll
        for (int rr = 0; rr < 2; rr++) {
            int m = m0 + wm * 32 + mi * 16 + gid + rr * 8;
            if (m < M) {
                float* yr = Y + ((size_t)b * Arows_per_b + m) * ldy;
#pragma unroll
                for (int ni = 0; ni < 4; ni++) {
                    int n = n0 + wn * 32 + ni * 8 + tig * 2;
                    float v0 = acc[mi][ni][rr * 2 + 0];
                    float v1 = acc[mi][ni][rr * 2 + 1];
                    if (mode == 0) {
                        v0 += bias[n];     v1 += bias[n + 1];
                        v0 = (v0 > 0.f) ? v0 : 0.01f * v0;
                        v1 = (v1 > 0.f) ? v1 : 0.01f * v1;
                    }
                    yr[n] = v0;
                    yr[n + 1] = v1;
                }
            }
        }
    }
}

// ---------------------------------------------------------------------------
__global__ void softmax_kernel(const int* __restrict__ Qmask) {
    int b = blockIdx.y, j = blockIdx.x;
    if (j >= g_cnt[b]) return;
    float* row = g_S + ((size_t)b * LC + j) * LQ;
    int t = threadIdx.x;
    int lane = t & 31, warp = t >> 5;
    float v0 = row[t];
    float v1 = row[t + 256];
    if (Qmask[b * LQ + t] == 0) v0 = NEG_INF;
    if (Qmask[b * LQ + t + 256] == 0) v1 = NEG_INF;

    __shared__ float red[8];
    __shared__ float bcast;

    float m = fmaxf(v0, v1);
#pragma unroll
    for (int o = 16; o; o >>= 1) m = fmaxf(m, __shfl_xor_sync(0xffffffffu, m, o));
    if (lane == 0) red[warp] = m;
    __syncthreads();
    if (t < 32) {
        float x = (t < 8) ? red[t] : -3.4e38f;
#pragma unroll
        for (int o = 4; o; o >>= 1) x = fmaxf(x, __shfl_xor_sync(0xffffffffu, x, o));
        if (t == 0) bcast = x;
    }
    __syncthreads();
    m = bcast;
    float e0 = expf(v0 - m), e1 = expf(v1 - m);
    float sum = e0 + e1;
#pragma unroll
    for (int o = 16; o; o >>= 1) sum += __shfl_xor_sync(0xffffffffu, sum, o);
    __syncthreads();
    if (lane == 0) red[warp] = sum;
    __syncthreads();
    if (t < 32) {
        float x = (t < 8) ? red[t] : 0.f;
#pragma unroll
        for (int o = 4; o; o >>= 1) x += __shfl_xor_sync(0xffffffffu, x, o);
        if (t == 0) bcast = x;
    }
    __syncthreads();
    float inv = 1.0f / bcast;
    row[t] = e0 * inv;
    row[t + 256] = e1 * inv;
}

// ---------------------------------------------------------------------------
// Final fused dual GEMM (Wf, Wg share A fragments), cat on the fly.
// ---------------------------------------------------------------------------
__global__ __launch_bounds__(256, 1)
void final_mma(const float* __restrict__ C, const float* __restrict__ Wf,
               const float* __restrict__ bfv, const float* __restrict__ Wg,
               const float* __restrict__ bgv, float* __restrict__ out) {
    int b  = blockIdx.z;
    int m0 = blockIdx.y * 128;
    int n0 = blockIdx.x * 64;
    int M  = g_cnt[b];
    if (m0 >= M) return;

    __shared__ __align__(16) uint4 sA[2][ACH];
    __shared__ __align__(16) uint4 sBf[2][BCH];
    __shared__ __align__(16) uint4 sBg[2][BCH];

    int tid = threadIdx.x;
    int am  = tid & 127, aks = tid >> 7;
    int bn  = tid & 63,  bkc = tid >> 6;

    int ja = min(m0 + am, M - 1);
    int ca = g_idx[b * LC + ja];
    const float* Crow  = C   + ((size_t)b * LC + ca) * DD;
    const float* Arow  = g_A + ((size_t)b * LC + ja) * DD;
    const float* Bfrow = Wf + (size_t)(n0 + bn) * D4 + bkc * 8;
    const float* Bgrow = Wg + (size_t)(n0 + bn) * D4 + bkc * 8;

    int lane = tid & 31, w = tid >> 5;
    int wm = w >> 1, wn = w & 1;
    int a_off = (wm * 32 + (lane & 15)) * 5 + (lane >> 4);
    int b_off = (wn * 32 + ((lane >> 4) << 3) + (lane & 7)) * 5 + ((lane >> 3) & 1);

    float accf[2][4][4], accg[2][4][4];
#pragma unroll
    for (int mi = 0; mi < 2; mi++)
#pragma unroll
        for (int ni = 0; ni < 4; ni++)
#pragma unroll
            for (int r = 0; r < 4; r++) { accf[mi][ni][r] = 0.f; accg[mi][ni][r] = 0.f; }

    unsigned ra[8], rbf[4], rbg[4];

#define LOAD_CAT(rr_, kg0_)                                                    \
    {                                                                          \
        int seg = (kg0_) >> 9;                                                 \
        int kk  = (kg0_) & 511;                                                \
        float4 cc[4], aa[4];                                                   \
        cc[0] = *(const float4*)(Crow + kk);                                   \
        cc[1] = *(const float4*)(Crow + kk + 4);                               \
        cc[2] = *(const float4*)(Crow + kk + 8);                               \
        cc[3] = *(const float4*)(Crow + kk + 12);                              \
        aa[0] = *(const float4*)(Arow + kk);                                   \
        aa[1] = *(const float4*)(Arow + kk + 4);                               \
        aa[2] = *(const float4*)(Arow + kk + 8);                               \
        aa[3] = *(const float4*)(Arow + kk + 12);                              \
        _Pragma("unroll")                                                      \
        for (int u = 0; u < 4; u++) {                                          \
            float4 cv = cc[u], av4 = aa[u], x;                                 \
            if (seg == 0)      x = cv;                                         \
            else if (seg == 1) x = av4;                                        \
            else if (seg == 2) x = make_float4(av4.x - cv.x, av4.y - cv.y,     \
                                               av4.z - cv.z, av4.w - cv.w);    \
            else               x = make_float4(av4.x * cv.x, av4.y * cv.y,     \
                                               av4.z * cv.z, av4.w * cv.w);    \
            (rr_)[u * 2 + 0] = pk(x.x, x.y);                                   \
            (rr_)[u * 2 + 1] = pk(x.z, x.w);                                   \
        }                                                                      \
    }

    LOAD_CAT(ra, aks * 16);
    loadB8(rbf, Bfrow);
    loadB8(rbg, Bgrow);

    const int KIT = D4 / 32;
    for (int it = 0; it < KIT; it++) {
        int buf = it & 1;
        sA[buf][am * 5 + aks * 2 + 0] = make_uint4(ra[0], ra[1], ra[2], ra[3]);
        sA[buf][am * 5 + aks * 2 + 1] = make_uint4(ra[4], ra[5], ra[6], ra[7]);
        sBf[buf][bn * 5 + bkc] = make_uint4(rbf[0], rbf[1], rbf[2], rbf[3]);
        sBg[buf][bn * 5 + bkc] = make_uint4(rbg[0], rbg[1], rbg[2], rbg[3]);
        __syncthreads();
        if (it + 1 < KIT) {
            LOAD_CAT(ra, (it + 1) * 32 + aks * 16);
            loadB8(rbf, Bfrow + (it + 1) * 32);
            loadB8(rbg, Bgrow + (it + 1) * 32);
        }
        unsigned abase  = sptr(&sA[buf][0]);
        unsigned bfbase = sptr(&sBf[buf][0]);
        unsigned bgbase = sptr(&sBg[buf][0]);
#pragma unroll
        for (int ks = 0; ks < 2; ks++) {
            unsigned av[2][4], bvf[2][4], bvg[2][4];
#pragma unroll
            for (int mi = 0; mi < 2; mi++)
                ldsm4(av[mi], abase + (unsigned)(a_off + mi * 16 * 5 + ks * 2) * 16);
#pragma unroll
            for (int np = 0; np < 2; np++) {
                ldsm4(bvf[np], bfbase + (unsigned)(b_off + np * 16 * 5 + ks * 2) * 16);
                ldsm4(bvg[np], bgbase + (unsigned)(b_off + np * 16 * 5 + ks * 2) * 16);
            }
#pragma unroll
            for (int mi = 0; mi < 2; mi++)
#pragma unroll
                for (int ni = 0; ni < 4; ni++) {
                    unsigned bf2[2] = { bvf[ni >> 1][(ni & 1) * 2 + 0],
                                        bvf[ni >> 1][(ni & 1) * 2 + 1] };
                    unsigned bg2[2] = { bvg[ni >> 1][(ni & 1) * 2 + 0],
                                        bvg[ni >> 1][(ni & 1) * 2 + 1] };
                    mma_bf16(accf[mi][ni], av[mi], bf2);
                    mma_bf16(accg[mi][ni], av[mi], bg2);
                }
        }
        __syncthreads();
    }

    int gid = lane >> 2, tig = lane & 3;
    int segn = n0 >> 9;
#pragma unroll
    for (int mi = 0; mi < 2; mi++) {
#pragma unroll
        for (int rr = 0; rr < 2; rr++) {
            int jrow = m0 + wm * 32 + mi * 16 + gid + rr * 8;
            if (jrow < M) {
                int c = g_idx[b * LC + jrow];
                const float* crow = C   + ((size_t)b * LC + c) * DD;
                const float* arow = g_A + ((size_t)b * LC + jrow) * DD;
                float* orow = out + ((size_t)b * LC + c) * (size_t)D4;
#pragma unroll
                for (int ni = 0; ni < 4; ni++) {
#pragma unroll
                    for (int e = 0; e < 2; e++) {
                        int n = n0 + wn * 32 + ni * 8 + tig * 2 + e;
                        int nn = n & 511;
                        float cval = crow[nn];
                        float aval = arow[nn];
                        float catv = (segn == 0) ? cval
                                   : (segn == 1) ? aval
                                   : (segn == 2) ? (aval - cval)
                                                 : (aval * cval);
                        float df = accf[mi][ni][rr * 2 + e];
                        float dg = accg[mi][ni][rr * 2 + e];
                        float fv = tanhf(df + bfv[n]);
                        float gv = 1.0f / (1.0f + __expf(-(dg + bgv[n])));
                        orow[n] = gv * fv + (1.0f - gv) * catv;
                    }
                }
            }
        }
    }
}

// ---------------------------------------------------------------------------
extern "C" void kernel_launch(void* const* d_in, const int* in_sizes, int n_in,
                              void* d_out, int out_size) {
    const float* C     = (const float*)d_in[0];
    const float* Q     = (const float*)d_in[1];
    const int*   Cmask = (const int*)d_in[2];
    const int*   Qmask = (const int*)d_in[3];
    const float* W1    = (const float*)d_in[4];
    const float* b1    = (const float*)d_in[5];
    const float* Wf    = (const float*)d_in[6];
    const float* bfv   = (const float*)d_in[7];
    const float* Wg    = (const float*)d_in[8];
    const float* bgv   = (const float*)d_in[9];
    float* out = (float*)d_out;

    float* dCp; cudaGetSymbolAddress((void**)&dCp, g_Cp);
    float* dQp; cudaGetSymbolAddress((void**)&dQp, g_Qp);
    float* dS;  cudaGetSymbolAddress((void**)&dS,  g_S);
    float* dA;  cudaGetSymbolAddress((void**)&dA,  g_A);
    float* dQt; cudaGetSymbolAddress((void**)&dQt, g_Qt);

    compact_kernel<<<NB, 256>>>(Cmask);
    fill_masked_kernel<<<dim3(1, LC, NB), 128>>>(Cmask, out);
    transpose_q_kernel<<<dim3(DD / 32, LQ / 32, NB), dim3(32, 8)>>>(Q);

    // C_ = lrelu(C@W1^T + b1), compacted rows
    gemm_nt_mma<<<dim3(DD / 64, LC / 128, NB), 256>>>(
        C, DD, LC, W1, DD, 0, dCp, DD, b1, DD, LC, 1, 1, 0);
    // Q_ = lrelu(Q@W1^T + b1), all rows
    gemm_nt_mma<<<dim3(DD / 64, LQ / 128, NB), 256>>>(
        Q, DD, LQ, W1, DD, 0, dQp, DD, b1, DD, LQ, 0, 0, 0);
    // S = C_ @ Q_^T (compacted c; batched B = g_Qp)
    gemm_nt_mma<<<dim3(LQ / 64, LC / 128, NB), 256>>>(
        dCp, DD, LC, dQp, DD, LQ, dS, LQ, b1, DD, LC, 1, 0, 1);
    softmax_kernel<<<dim3(LC, NB), 256>>>(Qmask);
    // attn_C = S_ @ Qt^T (compacted c; batched B = g_Qt)
    gemm_nt_mma<<<dim3(DD / 64, LC / 128, NB), 256>>>(
        dS, LQ, LC, dQt, LQ, DD, dA, DD, b1, LQ, LC, 1, 0, 1);
    // out = gate*tanh(cat@Wf^T+bf) + (1-gate)*cat  (compacted c rows)
    final_mma<<<dim3(D4 / 64, LC / 128, NB), 256>>>(C, Wf, bfv, Wg, bgv, out);
}

// round 6
// speedup vs baseline: 2.7629x; 2.7629x over previous
#include <cuda_runtime.h>
#include <cuda_bf16.h>
#include <math.h>

#define NEG_INF (-1e30f)
#define NB 16
#define LC 2048
#define LQ 512
#define DD 512
#define D4 2048

typedef __nv_bfloat16 bf16;

// bf16 scratch (converted once per launch)
__device__ bf16  g_Cb [NB * LC * DD];
__device__ bf16  g_Qb [NB * LQ * DD];
__device__ bf16  g_Qtb[NB * DD * LQ];
__device__ bf16  g_W1b[DD * DD];
__device__ bf16  g_Wfb[D4 * D4];
__device__ bf16  g_Wgb[D4 * D4];
__device__ bf16  g_Cpb[NB * LC * DD];
__device__ bf16  g_Qpb[NB * LQ * DD];
__device__ float g_S  [NB * LC * LQ];
__device__ bf16  g_Sb [NB * LC * LQ];
__device__ bf16  g_Ab [NB * LC * DD];
__device__ int   g_idx[NB * LC];
__device__ int   g_cnt[NB];

// ---------------------------------------------------------------------------
__device__ __forceinline__ unsigned pk(float a, float b) {
    __nv_bfloat162 h = __floats2bfloat162_rn(a, b);
    return *reinterpret_cast<unsigned*>(&h);
}

__device__ __forceinline__ void mma_bf16(float* d, const unsigned* a, const unsigned* b) {
    asm volatile(
        "mma.sync.aligned.m16n8k16.row.col.f32.bf16.bf16.f32 "
        "{%0,%1,%2,%3}, {%4,%5,%6,%7}, {%8,%9}, {%0,%1,%2,%3};\n"
        : "+f"(d[0]), "+f"(d[1]), "+f"(d[2]), "+f"(d[3])
        : "r"(a[0]), "r"(a[1]), "r"(a[2]), "r"(a[3]), "r"(b[0]), "r"(b[1]));
}

__device__ __forceinline__ void ldsm4(unsigned* r, unsigned addr) {
    asm volatile("ldmatrix.sync.aligned.m8n8.x4.shared.b16 {%0,%1,%2,%3}, [%4];"
                 : "=r"(r[0]), "=r"(r[1]), "=r"(r[2]), "=r"(r[3]) : "r"(addr));
}

__device__ __forceinline__ unsigned sptr(const void* p) {
    return (unsigned)__cvta_generic_to_shared(p);
}

__device__ __forceinline__ void cpasync16(unsigned dst, const void* src) {
    asm volatile("cp.async.cg.shared.global [%0], [%1], 16;\n" :: "r"(dst), "l"(src));
}
__device__ __forceinline__ void cpcommit() {
    asm volatile("cp.async.commit_group;\n" ::: "memory");
}
template <int N> __device__ __forceinline__ void cpwait() {
    asm volatile("cp.async.wait_group %0;\n" :: "n"(N) : "memory");
}

// SMEM: row-major bf16 tiles, row stride = 5 x 16B chunks (80B).
// (5r + c) mod 8 permutes bank-groups -> ldmatrix conflict-free, no swizzle.
#define ACH (128 * 5)
#define BCH (64 * 5)

// ---------------------------------------------------------------------------
__global__ void compact_kernel(const int* __restrict__ Cmask) {
    __shared__ int toff[257];
    int b = blockIdx.x;
    int t = threadIdx.x;
    int flags[8];
    int s = 0;
#pragma unroll
    for (int i = 0; i < 8; i++) {
        flags[i] = (Cmask[b * LC + t * 8 + i] != 0) ? 1 : 0;
        s += flags[i];
    }
    toff[t + 1] = s;
    __syncthreads();
    if (t == 0) {
        toff[0] = 0;
        for (int i = 1; i <= 256; i++) toff[i] += toff[i - 1];
        g_cnt[b] = toff[256];
    }
    __syncthreads();
    int pos = toff[t];
#pragma unroll
    for (int i = 0; i < 8; i++) {
        if (flags[i]) g_idx[b * LC + (pos++)] = t * 8 + i;
    }
}

__global__ void fill_masked_kernel(const int* __restrict__ Cmask,
                                   float* __restrict__ out) {
    int c = blockIdx.y;
    int b = blockIdx.z;
    if (Cmask[b * LC + c] != 0) return;
    float4* p = (float4*)(out + ((size_t)(b * LC + c)) * D4);
    float4 v = make_float4(NEG_INF, NEG_INF, NEG_INF, NEG_INF);
    int t = threadIdx.x;
    p[t] = v; p[t + 128] = v; p[t + 256] = v; p[t + 384] = v;
}

// fp32 -> bf16 bulk convert (8 elems / thread)
__global__ void cvt_kernel(const float* __restrict__ src, bf16* __restrict__ dst,
                           int n8) {
    int i = blockIdx.x * blockDim.x + threadIdx.x;
    if (i >= n8) return;
    const float4* s = (const float4*)src + (size_t)i * 2;
    float4 a = s[0], b = s[1];
    uint4 o;
    o.x = pk(a.x, a.y); o.y = pk(a.z, a.w);
    o.z = pk(b.x, b.y); o.w = pk(b.z, b.w);
    ((uint4*)dst)[i] = o;
}

// Q fp32 -> transposed bf16: g_Qtb[b][d][q]
__global__ void transpose_q_kernel(const float* __restrict__ Q) {
    __shared__ float t[32][33];
    int b = blockIdx.z;
    int d0 = blockIdx.x * 32, q0 = blockIdx.y * 32;
    int tx = threadIdx.x, ty = threadIdx.y;
#pragma unroll
    for (int i = 0; i < 4; i++)
        t[ty + i * 8][tx] = Q[((size_t)b * LQ + q0 + ty + i * 8) * DD + d0 + tx];
    __syncthreads();
#pragma unroll
    for (int i = 0; i < 4; i++)
        g_Qtb[((size_t)b * DD + d0 + ty + i * 8) * LQ + q0 + tx] =
            __float2bfloat16(t[tx][ty + i * 8]);
}

// ---------------------------------------------------------------------------
// Generic bf16 NT GEMM: 3-stage cp.async pipeline, ldmatrix consumer.
// BM=128 BN=64 BK=32, 256 threads (8 warps = 4m x 2n of 32x32).
// mode 0: bias + leaky_relu -> bf16; mode 1: fp32 out; mode 2: bf16 out.
// ---------------------------------------------------------------------------
__global__ __launch_bounds__(256, 2)
void gemm_bf16(const bf16* __restrict__ A, int lda, int Arows_per_b,
               const bf16* __restrict__ B, int ldb, int Brows_per_b,
               void* __restrict__ Yv, int ldy,
               const float* __restrict__ bias,
               int K, int Mfull, int use_cnt, int gather, int mode) {
    int b  = blockIdx.z;
    int m0 = blockIdx.y * 128;
    int n0 = blockIdx.x * 64;
    int M  = use_cnt ? g_cnt[b] : Mfull;
    if (m0 >= M) return;

    __shared__ __align__(16) uint4 sA[3][ACH];
    __shared__ __align__(16) uint4 sB[3][BCH];

    int tid = threadIdx.x;
    // producers: A thread -> (row ar, chunks ac, ac+1); B -> (row br, chunk bc)
    int ar = tid >> 1, ac = (tid & 1) * 2;
    int br = tid >> 2, bc = tid & 3;
    int j = min(m0 + ar, M - 1);
    int srow = gather ? g_idx[b * LC + j] : j;
    const bf16* Asrc = A + ((size_t)b * Arows_per_b + srow) * lda + ac * 8;
    const bf16* Bsrc = B + ((size_t)b * Brows_per_b + n0 + br) * ldb + bc * 8;
    unsigned adst0 = sptr(&sA[0][0]) + (unsigned)(ar * 5 + ac) * 16;
    unsigned bdst0 = sptr(&sB[0][0]) + (unsigned)(br * 5 + bc) * 16;

    int lane = tid & 31, w = tid >> 5;
    int wm = w >> 1, wn = w & 1;
    int a_off = (wm * 32 + (lane & 15)) * 5 + (lane >> 4);
    int b_off = (wn * 32 + ((lane >> 4) << 3) + (lane & 7)) * 5 + ((lane >> 3) & 1);

    float acc[2][4][4];
#pragma unroll
    for (int mi = 0; mi < 2; mi++)
#pragma unroll
        for (int ni = 0; ni < 4; ni++)
#pragma unroll
            for (int r = 0; r < 4; r++) acc[mi][ni][r] = 0.f;

    const int KIT = K / 32;

#define ISSUE(it_)                                                          \
    {                                                                       \
        int st_ = (it_) % 3;                                                \
        cpasync16(adst0 + (unsigned)st_ * (ACH * 16), Asrc + (it_) * 32);   \
        cpasync16(adst0 + (unsigned)st_ * (ACH * 16) + 16,                  \
                  Asrc + (it_) * 32 + 8);                                   \
        cpasync16(bdst0 + (unsigned)st_ * (BCH * 16), Bsrc + (it_) * 32);   \
    }

    ISSUE(0); cpcommit();
    if (KIT > 1) { ISSUE(1); } cpcommit();

    for (int it = 0; it < KIT; it++) {
        cpwait<1>();
        __syncthreads();
        if (it + 2 < KIT) { ISSUE(it + 2); }
        cpcommit();
        int st = it % 3;
        unsigned abase = sptr(&sA[st][0]);
        unsigned bbase = sptr(&sB[st][0]);
#pragma unroll
        for (int ks = 0; ks < 2; ks++) {
            unsigned av[2][4], bv[2][4];
#pragma unroll
            for (int mi = 0; mi < 2; mi++)
                ldsm4(av[mi], abase + (unsigned)(a_off + mi * 16 * 5 + ks * 2) * 16);
#pragma unroll
            for (int np = 0; np < 2; np++)
                ldsm4(bv[np], bbase + (unsigned)(b_off + np * 16 * 5 + ks * 2) * 16);
#pragma unroll
            for (int mi = 0; mi < 2; mi++)
#pragma unroll
                for (int ni = 0; ni < 4; ni++) {
                    unsigned bb[2] = { bv[ni >> 1][(ni & 1) * 2 + 0],
                                       bv[ni >> 1][(ni & 1) * 2 + 1] };
                    mma_bf16(acc[mi][ni], av[mi], bb);
                }
        }
    }
#undef ISSUE

    int gid = lane >> 2, tig = lane & 3;
#pragma unroll
    for (int mi = 0; mi < 2; mi++) {
#pragma unroll
        for (int rr = 0; rr < 2; rr++) {
            int m = m0 + wm * 32 + mi * 16 + gid + rr * 8;
            if (m >= M) continue;
            if (mode == 1) {
                float* yr = (float*)Yv + ((size_t)b * Arows_per_b + m) * ldy;
#pragma unroll
                for (int ni = 0; ni < 4; ni++) {
                    int n = n0 + wn * 32 + ni * 8 + tig * 2;
                    yr[n]     = acc[mi][ni][rr * 2 + 0];
                    yr[n + 1] = acc[mi][ni][rr * 2 + 1];
                }
            } else {
                bf16* yr = (bf16*)Yv + ((size_t)b * Arows_per_b + m) * ldy;
#pragma unroll
                for (int ni = 0; ni < 4; ni++) {
                    int n = n0 + wn * 32 + ni * 8 + tig * 2;
                    float v0 = acc[mi][ni][rr * 2 + 0];
                    float v1 = acc[mi][ni][rr * 2 + 1];
                    if (mode == 0) {
                        v0 += bias[n];     v1 += bias[n + 1];
                        v0 = (v0 > 0.f) ? v0 : 0.01f * v0;
                        v1 = (v1 > 0.f) ? v1 : 0.01f * v1;
                    }
                    *(__nv_bfloat162*)(yr + n) = __floats2bfloat162_rn(v0, v1);
                }
            }
        }
    }
}

// ---------------------------------------------------------------------------
// Softmax over q with Qmask: reads fp32 g_S, writes bf16 g_Sb.
// ---------------------------------------------------------------------------
__global__ void softmax_kernel(const int* __restrict__ Qmask) {
    int b = blockIdx.y, j = blockIdx.x;
    if (j >= g_cnt[b]) return;
    const float* row = g_S + ((size_t)b * LC + j) * LQ;
    bf16* orow = g_Sb + ((size_t)b * LC + j) * LQ;
    int t = threadIdx.x;
    int lane = t & 31, warp = t >> 5;
    float v0 = row[t];
    float v1 = row[t + 256];
    if (Qmask[b * LQ + t] == 0) v0 = NEG_INF;
    if (Qmask[b * LQ + t + 256] == 0) v1 = NEG_INF;

    __shared__ float red[8];
    __shared__ float bcast;

    float m = fmaxf(v0, v1);
#pragma unroll
    for (int o = 16; o; o >>= 1) m = fmaxf(m, __shfl_xor_sync(0xffffffffu, m, o));
    if (lane == 0) red[warp] = m;
    __syncthreads();
    if (t < 32) {
        float x = (t < 8) ? red[t] : -3.4e38f;
#pragma unroll
        for (int o = 4; o; o >>= 1) x = fmaxf(x, __shfl_xor_sync(0xffffffffu, x, o));
        if (t == 0) bcast = x;
    }
    __syncthreads();
    m = bcast;
    float e0 = expf(v0 - m), e1 = expf(v1 - m);
    float sum = e0 + e1;
#pragma unroll
    for (int o = 16; o; o >>= 1) sum += __shfl_xor_sync(0xffffffffu, sum, o);
    __syncthreads();
    if (lane == 0) red[warp] = sum;
    __syncthreads();
    if (t < 32) {
        float x = (t < 8) ? red[t] : 0.f;
#pragma unroll
        for (int o = 4; o; o >>= 1) x += __shfl_xor_sync(0xffffffffu, x, o);
        if (t == 0) bcast = x;
    }
    __syncthreads();
    float inv = 1.0f / bcast;
    orow[t]       = __float2bfloat16(e0 * inv);
    orow[t + 256] = __float2bfloat16(e1 * inv);
}

// ---------------------------------------------------------------------------
// Final fused dual GEMM: bf16 cat built on the fly (from g_Cb, g_Ab),
// Wf/Wg share A fragments; R2-style single-sync double buffer.
// ---------------------------------------------------------------------------
__device__ __forceinline__ uint4 catchunk(uint4 c, uint4 a, int seg) {
    if (seg == 0) return c;
    if (seg == 1) return a;
    uint4 r;
    const __nv_bfloat162* cp = (const __nv_bfloat162*)&c;
    const __nv_bfloat162* ap = (const __nv_bfloat162*)&a;
    __nv_bfloat162* rp = (__nv_bfloat162*)&r;
    if (seg == 2) {
#pragma unroll
        for (int i = 0; i < 4; i++) rp[i] = __hsub2(ap[i], cp[i]);
    } else {
#pragma unroll
        for (int i = 0; i < 4; i++) rp[i] = __hmul2(ap[i], cp[i]);
    }
    return r;
}

__global__ __launch_bounds__(256)
void final_mma(const float* __restrict__ bfv, const float* __restrict__ bgv,
               float* __restrict__ out) {
    int b  = blockIdx.z;
    int m0 = blockIdx.y * 128;
    int n0 = blockIdx.x * 64;
    int M  = g_cnt[b];
    if (m0 >= M) return;

    __shared__ __align__(16) uint4 sA [2][ACH];
    __shared__ __align__(16) uint4 sBf[2][BCH];
    __shared__ __align__(16) uint4 sBg[2][BCH];

    int tid = threadIdx.x;
    int ar = tid >> 1, ac = (tid & 1) * 2;
    int br = tid >> 2, bc = tid & 3;

    int ja = min(m0 + ar, M - 1);
    int ca = g_idx[b * LC + ja];
    const bf16* Crow  = g_Cb + ((size_t)b * LC + ca) * DD;
    const bf16* Arow  = g_Ab + ((size_t)b * LC + ja) * DD;
    const bf16* Bfrow = g_Wfb + (size_t)(n0 + br) * D4 + bc * 8;
    const bf16* Bgrow = g_Wgb + (size_t)(n0 + br) * D4 + bc * 8;

    int lane = tid & 31, w = tid >> 5;
    int wm = w >> 1, wn = w & 1;
    int a_off = (wm * 32 + (lane & 15)) * 5 + (lane >> 4);
    int b_off = (wn * 32 + ((lane >> 4) << 3) + (lane & 7)) * 5 + ((lane >> 3) & 1);

    float accf[2][4][4], accg[2][4][4];
#pragma unroll
    for (int mi = 0; mi < 2; mi++)
#pragma unroll
        for (int ni = 0; ni < 4; ni++)
#pragma unroll
            for (int r = 0; r < 4; r++) { accf[mi][ni][r] = 0.f; accg[mi][ni][r] = 0.f; }

    uint4 rc[2], raa[2], rbf, rbg;

#define LOAD_REGS(it_)                                                       \
    {                                                                        \
        int kk_ = ((it_) * 32) & 511;                                        \
        rc[0]  = *(const uint4*)(Crow + kk_ + ac * 8);                       \
        rc[1]  = *(const uint4*)(Crow + kk_ + ac * 8 + 8);                   \
        raa[0] = *(const uint4*)(Arow + kk_ + ac * 8);                       \
        raa[1] = *(const uint4*)(Arow + kk_ + ac * 8 + 8);                   \
        rbf    = *(const uint4*)(Bfrow + (it_) * 32);                        \
        rbg    = *(const uint4*)(Bgrow + (it_) * 32);                        \
    }

    LOAD_REGS(0);

    const int KIT = D4 / 32;
    for (int it = 0; it < KIT; it++) {
        int buf = it & 1;
        int seg = it >> 4;   // 512 / 32
        sA [buf][ar * 5 + ac    ] = catchunk(rc[0], raa[0], seg);
        sA [buf][ar * 5 + ac + 1] = catchunk(rc[1], raa[1], seg);
        sBf[buf][br * 5 + bc] = rbf;
        sBg[buf][br * 5 + bc] = rbg;
        __syncthreads();
        if (it + 1 < KIT) { LOAD_REGS(it + 1); }
        unsigned abase  = sptr(&sA [buf][0]);
        unsigned bfbase = sptr(&sBf[buf][0]);
        unsigned bgbase = sptr(&sBg[buf][0]);
#pragma unroll
        for (int ks = 0; ks < 2; ks++) {
            unsigned av[2][4], bvf[2][4], bvg[2][4];
#pragma unroll
            for (int mi = 0; mi < 2; mi++)
                ldsm4(av[mi], abase + (unsigned)(a_off + mi * 16 * 5 + ks * 2) * 16);
#pragma unroll
            for (int np = 0; np < 2; np++) {
                ldsm4(bvf[np], bfbase + (unsigned)(b_off + np * 16 * 5 + ks * 2) * 16);
                ldsm4(bvg[np], bgbase + (unsigned)(b_off + np * 16 * 5 + ks * 2) * 16);
            }
#pragma unroll
            for (int mi = 0; mi < 2; mi++)
#pragma unroll
                for (int ni = 0; ni < 4; ni++) {
                    unsigned bf2[2] = { bvf[ni >> 1][(ni & 1) * 2 + 0],
                                        bvf[ni >> 1][(ni & 1) * 2 + 1] };
                    unsigned bg2[2] = { bvg[ni >> 1][(ni & 1) * 2 + 0],
                                        bvg[ni >> 1][(ni & 1) * 2 + 1] };
                    mma_bf16(accf[mi][ni], av[mi], bf2);
                    mma_bf16(accg[mi][ni], av[mi], bg2);
                }
        }
    }
#undef LOAD_REGS

    int gid = lane >> 2, tig = lane & 3;
    int segn = n0 >> 9;
#pragma unroll
    for (int mi = 0; mi < 2; mi++) {
#pragma unroll
        for (int rr = 0; rr < 2; rr++) {
            int jrow = m0 + wm * 32 + mi * 16 + gid + rr * 8;
            if (jrow < M) {
                int c = g_idx[b * LC + jrow];
                const bf16* crow = g_Cb + ((size_t)b * LC + c) * DD;
                const bf16* arow = g_Ab + ((size_t)b * LC + jrow) * DD;
                float* orow = out + ((size_t)b * LC + c) * (size_t)D4;
#pragma unroll
                for (int ni = 0; ni < 4; ni++) {
#pragma unroll
                    for (int e = 0; e < 2; e++) {
                        int n = n0 + wn * 32 + ni * 8 + tig * 2 + e;
                        int nn = n & 511;
                        float cval = __bfloat162float(crow[nn]);
                        float aval = __bfloat162float(arow[nn]);
                        float catv = (segn == 0) ? cval
                                   : (segn == 1) ? aval
                                   : (segn == 2) ? (aval - cval)
                                                 : (aval * cval);
                        float df = accf[mi][ni][rr * 2 + e];
                        float dg = accg[mi][ni][rr * 2 + e];
                        float fv = tanhf(df + bfv[n]);
                        float gv = 1.0f / (1.0f + __expf(-(dg + bgv[n])));
                        orow[n] = gv * fv + (1.0f - gv) * catv;
                    }
                }
            }
        }
    }
}

// ---------------------------------------------------------------------------
extern "C" void kernel_launch(void* const* d_in, const int* in_sizes, int n_in,
                              void* d_out, int out_size) {
    const float* C     = (const float*)d_in[0];
    const float* Q     = (const float*)d_in[1];
    const int*   Cmask = (const int*)d_in[2];
    const int*   Qmask = (const int*)d_in[3];
    const float* W1    = (const float*)d_in[4];
    const float* b1    = (const float*)d_in[5];
    const float* Wf    = (const float*)d_in[6];
    const float* bfv   = (const float*)d_in[7];
    const float* Wg    = (const float*)d_in[8];
    const float* bgv   = (const float*)d_in[9];
    float* out = (float*)d_out;

    bf16* dCb;  cudaGetSymbolAddress((void**)&dCb,  g_Cb);
    bf16* dQb;  cudaGetSymbolAddress((void**)&dQb,  g_Qb);
    bf16* dQtb; cudaGetSymbolAddress((void**)&dQtb, g_Qtb);
    bf16* dW1b; cudaGetSymbolAddress((void**)&dW1b, g_W1b);
    bf16* dWfb; cudaGetSymbolAddress((void**)&dWfb, g_Wfb);
    bf16* dWgb; cudaGetSymbolAddress((void**)&dWgb, g_Wgb);
    bf16* dCpb; cudaGetSymbolAddress((void**)&dCpb, g_Cpb);
    bf16* dQpb; cudaGetSymbolAddress((void**)&dQpb, g_Qpb);
    float* dS;  cudaGetSymbolAddress((void**)&dS,   g_S);
    bf16* dSb;  cudaGetSymbolAddress((void**)&dSb,  g_Sb);
    bf16* dAb;  cudaGetSymbolAddress((void**)&dAb,  g_Ab);

    compact_kernel<<<NB, 256>>>(Cmask);
    fill_masked_kernel<<<dim3(1, LC, NB), 128>>>(Cmask, out);

    // one-time fp32 -> bf16 conversions
    cvt_kernel<<<(NB * LC * DD / 8 + 255) / 256, 256>>>(C,  dCb,  NB * LC * DD / 8);
    cvt_kernel<<<(NB * LQ * DD / 8 + 255) / 256, 256>>>(Q,  dQb,  NB * LQ * DD / 8);
    cvt_kernel<<<(DD * DD / 8 + 255) / 256, 256>>>(W1, dW1b, DD * DD / 8);
    cvt_kernel<<<(D4 * D4 / 8 + 255) / 256, 256>>>(Wf, dWfb, D4 * D4 / 8);
    cvt_kernel<<<(D4 * D4 / 8 + 255) / 256, 256>>>(Wg, dWgb, D4 * D4 / 8);
    transpose_q_kernel<<<dim3(DD / 32, LQ / 32, NB), dim3(32, 8)>>>(Q);

    // C_ = lrelu(C@W1^T + b1), compacted rows
    gemm_bf16<<<dim3(DD / 64, LC / 128, NB), 256>>>(
        dCb, DD, LC, dW1b, DD, 0, dCpb, DD, b1, DD, LC, 1, 1, 0);
    // Q_ = lrelu(Q@W1^T + b1), all rows
    gemm_bf16<<<dim3(DD / 64, LQ / 128, NB), 256>>>(
        dQb, DD, LQ, dW1b, DD, 0, dQpb, DD, b1, DD, LQ, 0, 0, 0);
    // S = C_ @ Q_^T (compacted c; batched B) -> fp32
    gemm_bf16<<<dim3(LQ / 64, LC / 128, NB), 256>>>(
        dCpb, DD, LC, dQpb, DD, LQ, dS, LQ, b1, DD, LC, 1, 0, 1);
    // masked softmax -> bf16 probabilities
    softmax_kernel<<<dim3(LC, NB), 256>>>(Qmask);
    // attn_C = S_ @ Qt^T (compacted c; batched B) -> bf16
    gemm_bf16<<<dim3(DD / 64, LC / 128, NB), 256>>>(
        dSb, LQ, LC, dQtb, LQ, DD, dAb, DD, b1, LQ, LC, 1, 0, 2);
    // out = gate*tanh(cat@Wf^T+bf) + (1-gate)*cat  (compacted c rows)
    final_mma<<<dim3(D4 / 64, LC / 128, NB), 256>>>(bfv, bgv, out);
}

// round 7
// speedup vs baseline: 3.1757x; 1.1494x over previous
#include <cuda_runtime.h>
#include <cuda_bf16.h>
#include <math.h>

#define NEG_INF (-1e30f)
#define NB 16
#define LC 2048
#define LQ 512
#define DD 512
#define D4 2048

typedef __nv_bfloat16 bf16;

// bf16 scratch (converted once per launch)
__device__ bf16  g_Cb [NB * LC * DD];
__device__ bf16  g_Qb [NB * LQ * DD];
__device__ bf16  g_Qtb[NB * DD * LQ];
__device__ bf16  g_W1b[DD * DD];
__device__ bf16  g_Wfb[D4 * D4];
__device__ bf16  g_Wgb[D4 * D4];
__device__ bf16  g_Cpb[NB * LC * DD];
__device__ bf16  g_Qpb[NB * LQ * DD];
__device__ float g_S  [NB * LC * LQ];
__device__ bf16  g_Sb [NB * LC * LQ];
__device__ bf16  g_Ab [NB * LC * DD];
__device__ bf16  g_catb[(size_t)NB * LC * D4];   // materialized cat (compacted rows)
__device__ int   g_idx[NB * LC];
__device__ int   g_cnt[NB];

// ---------------------------------------------------------------------------
__device__ __forceinline__ unsigned pk(float a, float b) {
    __nv_bfloat162 h = __floats2bfloat162_rn(a, b);
    return *reinterpret_cast<unsigned*>(&h);
}

__device__ __forceinline__ void mma_bf16(float* d, const unsigned* a, const unsigned* b) {
    asm volatile(
        "mma.sync.aligned.m16n8k16.row.col.f32.bf16.bf16.f32 "
        "{%0,%1,%2,%3}, {%4,%5,%6,%7}, {%8,%9}, {%0,%1,%2,%3};\n"
        : "+f"(d[0]), "+f"(d[1]), "+f"(d[2]), "+f"(d[3])
        : "r"(a[0]), "r"(a[1]), "r"(a[2]), "r"(a[3]), "r"(b[0]), "r"(b[1]));
}

__device__ __forceinline__ void ldsm4(unsigned* r, unsigned addr) {
    asm volatile("ldmatrix.sync.aligned.m8n8.x4.shared.b16 {%0,%1,%2,%3}, [%4];"
                 : "=r"(r[0]), "=r"(r[1]), "=r"(r[2]), "=r"(r[3]) : "r"(addr));
}

__device__ __forceinline__ unsigned sptr(const void* p) {
    return (unsigned)__cvta_generic_to_shared(p);
}

__device__ __forceinline__ void cpasync16(unsigned dst, const void* src) {
    asm volatile("cp.async.cg.shared.global [%0], [%1], 16;\n" :: "r"(dst), "l"(src));
}
__device__ __forceinline__ void cpcommit() {
    asm volatile("cp.async.commit_group;\n" ::: "memory");
}
template <int N> __device__ __forceinline__ void cpwait() {
    asm volatile("cp.async.wait_group %0;\n" :: "n"(N) : "memory");
}

// SMEM: row-major bf16 tiles, row stride = 5 x 16B chunks (80B).
// (5r + c) mod 8 permutes bank-groups -> ldmatrix conflict-free, no swizzle.
#define ACH (128 * 5)
#define BCH (64 * 5)
#define FCH (128 * 5)   // final kernel B rows = 128

// ---------------------------------------------------------------------------
__global__ void compact_kernel(const int* __restrict__ Cmask) {
    __shared__ int toff[257];
    int b = blockIdx.x;
    int t = threadIdx.x;
    int flags[8];
    int s = 0;
#pragma unroll
    for (int i = 0; i < 8; i++) {
        flags[i] = (Cmask[b * LC + t * 8 + i] != 0) ? 1 : 0;
        s += flags[i];
    }
    toff[t + 1] = s;
    __syncthreads();
    if (t == 0) {
        toff[0] = 0;
        for (int i = 1; i <= 256; i++) toff[i] += toff[i - 1];
        g_cnt[b] = toff[256];
    }
    __syncthreads();
    int pos = toff[t];
#pragma unroll
    for (int i = 0; i < 8; i++) {
        if (flags[i]) g_idx[b * LC + (pos++)] = t * 8 + i;
    }
}

__global__ void fill_masked_kernel(const int* __restrict__ Cmask,
                                   float* __restrict__ out) {
    int c = blockIdx.y;
    int b = blockIdx.z;
    if (Cmask[b * LC + c] != 0) return;
    float4* p = (float4*)(out + ((size_t)(b * LC + c)) * D4);
    float4 v = make_float4(NEG_INF, NEG_INF, NEG_INF, NEG_INF);
    int t = threadIdx.x;
    p[t] = v; p[t + 128] = v; p[t + 256] = v; p[t + 384] = v;
}

// fp32 -> bf16 bulk convert (8 elems / thread)
__global__ void cvt_kernel(const float* __restrict__ src, bf16* __restrict__ dst,
                           int n8) {
    int i = blockIdx.x * blockDim.x + threadIdx.x;
    if (i >= n8) return;
    const float4* s = (const float4*)src + (size_t)i * 2;
    float4 a = s[0], b = s[1];
    uint4 o;
    o.x = pk(a.x, a.y); o.y = pk(a.z, a.w);
    o.z = pk(b.x, b.y); o.w = pk(b.z, b.w);
    ((uint4*)dst)[i] = o;
}

// Q fp32 -> transposed bf16: g_Qtb[b][d][q]
__global__ void transpose_q_kernel(const float* __restrict__ Q) {
    __shared__ float t[32][33];
    int b = blockIdx.z;
    int d0 = blockIdx.x * 32, q0 = blockIdx.y * 32;
    int tx = threadIdx.x, ty = threadIdx.y;
#pragma unroll
    for (int i = 0; i < 4; i++)
        t[ty + i * 8][tx] = Q[((size_t)b * LQ + q0 + ty + i * 8) * DD + d0 + tx];
    __syncthreads();
#pragma unroll
    for (int i = 0; i < 4; i++)
        g_Qtb[((size_t)b * DD + d0 + ty + i * 8) * LQ + q0 + tx] =
            __float2bfloat16(t[tx][ty + i * 8]);
}

// ---------------------------------------------------------------------------
// Generic bf16 NT GEMM: 3-stage cp.async pipeline, ldmatrix consumer.
// BM=128 BN=64 BK=32, 256 threads (8 warps = 4m x 2n of 32x32).
// mode 0: bias + leaky_relu -> bf16; mode 1: fp32 out; mode 2: bf16 out.
// ---------------------------------------------------------------------------
__global__ __launch_bounds__(256, 2)
void gemm_bf16(const bf16* __restrict__ A, int lda, int Arows_per_b,
               const bf16* __restrict__ B, int ldb, int Brows_per_b,
               void* __restrict__ Yv, int ldy,
               const float* __restrict__ bias,
               int K, int Mfull, int use_cnt, int gather, int mode) {
    int b  = blockIdx.z;
    int m0 = blockIdx.y * 128;
    int n0 = blockIdx.x * 64;
    int M  = use_cnt ? g_cnt[b] : Mfull;
    if (m0 >= M) return;

    __shared__ __align__(16) uint4 sA[3][ACH];
    __shared__ __align__(16) uint4 sB[3][BCH];

    int tid = threadIdx.x;
    int ar = tid >> 1, ac = (tid & 1) * 2;
    int br = tid >> 2, bc = tid & 3;
    int j = min(m0 + ar, M - 1);
    int srow = gather ? g_idx[b * LC + j] : j;
    const bf16* Asrc = A + ((size_t)b * Arows_per_b + srow) * lda + ac * 8;
    const bf16* Bsrc = B + ((size_t)b * Brows_per_b + n0 + br) * ldb + bc * 8;
    unsigned adst0 = sptr(&sA[0][0]) + (unsigned)(ar * 5 + ac) * 16;
    unsigned bdst0 = sptr(&sB[0][0]) + (unsigned)(br * 5 + bc) * 16;

    int lane = tid & 31, w = tid >> 5;
    int wm = w >> 1, wn = w & 1;
    int a_off = (wm * 32 + (lane & 15)) * 5 + (lane >> 4);
    int b_off = (wn * 32 + ((lane >> 4) << 3) + (lane & 7)) * 5 + ((lane >> 3) & 1);

    float acc[2][4][4];
#pragma unroll
    for (int mi = 0; mi < 2; mi++)
#pragma unroll
        for (int ni = 0; ni < 4; ni++)
#pragma unroll
            for (int r = 0; r < 4; r++) acc[mi][ni][r] = 0.f;

    const int KIT = K / 32;

#define ISSUE(it_)                                                          \
    {                                                                       \
        int st_ = (it_) % 3;                                                \
        cpasync16(adst0 + (unsigned)st_ * (ACH * 16), Asrc + (it_) * 32);   \
        cpasync16(adst0 + (unsigned)st_ * (ACH * 16) + 16,                  \
                  Asrc + (it_) * 32 + 8);                                   \
        cpasync16(bdst0 + (unsigned)st_ * (BCH * 16), Bsrc + (it_) * 32);   \
    }

    ISSUE(0); cpcommit();
    if (KIT > 1) { ISSUE(1); } cpcommit();

    for (int it = 0; it < KIT; it++) {
        cpwait<1>();
        __syncthreads();
        if (it + 2 < KIT) { ISSUE(it + 2); }
        cpcommit();
        int st = it % 3;
        unsigned abase = sptr(&sA[st][0]);
        unsigned bbase = sptr(&sB[st][0]);
#pragma unroll
        for (int ks = 0; ks < 2; ks++) {
            unsigned av[2][4], bv[2][4];
#pragma unroll
            for (int mi = 0; mi < 2; mi++)
                ldsm4(av[mi], abase + (unsigned)(a_off + mi * 16 * 5 + ks * 2) * 16);
#pragma unroll
            for (int np = 0; np < 2; np++)
                ldsm4(bv[np], bbase + (unsigned)(b_off + np * 16 * 5 + ks * 2) * 16);
#pragma unroll
            for (int mi = 0; mi < 2; mi++)
#pragma unroll
                for (int ni = 0; ni < 4; ni++) {
                    unsigned bb[2] = { bv[ni >> 1][(ni & 1) * 2 + 0],
                                       bv[ni >> 1][(ni & 1) * 2 + 1] };
                    mma_bf16(acc[mi][ni], av[mi], bb);
                }
        }
    }
#undef ISSUE

    int gid = lane >> 2, tig = lane & 3;
#pragma unroll
    for (int mi = 0; mi < 2; mi++) {
#pragma unroll
        for (int rr = 0; rr < 2; rr++) {
            int m = m0 + wm * 32 + mi * 16 + gid + rr * 8;
            if (m >= M) continue;
            if (mode == 1) {
                float* yr = (float*)Yv + ((size_t)b * Arows_per_b + m) * ldy;
#pragma unroll
                for (int ni = 0; ni < 4; ni++) {
                    int n = n0 + wn * 32 + ni * 8 + tig * 2;
                    yr[n]     = acc[mi][ni][rr * 2 + 0];
                    yr[n + 1] = acc[mi][ni][rr * 2 + 1];
                }
            } else {
                bf16* yr = (bf16*)Yv + ((size_t)b * Arows_per_b + m) * ldy;
#pragma unroll
                for (int ni = 0; ni < 4; ni++) {
                    int n = n0 + wn * 32 + ni * 8 + tig * 2;
                    float v0 = acc[mi][ni][rr * 2 + 0];
                    float v1 = acc[mi][ni][rr * 2 + 1];
                    if (mode == 0) {
                        v0 += bias[n];     v1 += bias[n + 1];
                        v0 = (v0 > 0.f) ? v0 : 0.01f * v0;
                        v1 = (v1 > 0.f) ? v1 : 0.01f * v1;
                    }
                    *(__nv_bfloat162*)(yr + n) = __floats2bfloat162_rn(v0, v1);
                }
            }
        }
    }
}

// ---------------------------------------------------------------------------
// Softmax over q with Qmask: reads fp32 g_S, writes bf16 g_Sb.
// ---------------------------------------------------------------------------
__global__ void softmax_kernel(const int* __restrict__ Qmask) {
    int b = blockIdx.y, j = blockIdx.x;
    if (j >= g_cnt[b]) return;
    const float* row = g_S + ((size_t)b * LC + j) * LQ;
    bf16* orow = g_Sb + ((size_t)b * LC + j) * LQ;
    int t = threadIdx.x;
    int lane = t & 31, warp = t >> 5;
    float v0 = row[t];
    float v1 = row[t + 256];
    if (Qmask[b * LQ + t] == 0) v0 = NEG_INF;
    if (Qmask[b * LQ + t + 256] == 0) v1 = NEG_INF;

    __shared__ float red[8];
    __shared__ float bcast;

    float m = fmaxf(v0, v1);
#pragma unroll
    for (int o = 16; o; o >>= 1) m = fmaxf(m, __shfl_xor_sync(0xffffffffu, m, o));
    if (lane == 0) red[warp] = m;
    __syncthreads();
    if (t < 32) {
        float x = (t < 8) ? red[t] : -3.4e38f;
#pragma unroll
        for (int o = 4; o; o >>= 1) x = fmaxf(x, __shfl_xor_sync(0xffffffffu, x, o));
        if (t == 0) bcast = x;
    }
    __syncthreads();
    m = bcast;
    float e0 = expf(v0 - m), e1 = expf(v1 - m);
    float sum = e0 + e1;
#pragma unroll
    for (int o = 16; o; o >>= 1) sum += __shfl_xor_sync(0xffffffffu, sum, o);
    __syncthreads();
    if (lane == 0) red[warp] = sum;
    __syncthreads();
    if (t < 32) {
        float x = (t < 8) ? red[t] : 0.f;
#pragma unroll
        for (int o = 4; o; o >>= 1) x += __shfl_xor_sync(0xffffffffu, x, o);
        if (t == 0) bcast = x;
    }
    __syncthreads();
    float inv = 1.0f / bcast;
    orow[t]       = __float2bfloat16(e0 * inv);
    orow[t + 256] = __float2bfloat16(e1 * inv);
}

// ---------------------------------------------------------------------------
// Materialize cat = [C | A | A-C | A*C] as bf16, compacted rows.
// ---------------------------------------------------------------------------
__global__ void cat_kernel(const float* __restrict__ C) {
    int b = blockIdx.y, j = blockIdx.x;
    if (j >= g_cnt[b]) return;
    int c = g_idx[b * LC + j];
    const float* crow = C + ((size_t)b * LC + c) * DD;
    const bf16* arow = g_Ab + ((size_t)b * LC + j) * DD;
    __nv_bfloat162* orow = (__nv_bfloat162*)(g_catb + ((size_t)b * LC + j) * D4);
    int t = threadIdx.x;   // 256 threads, 2 elems each
    int d = t * 2;
    float c0 = crow[d], c1 = crow[d + 1];
    __nv_bfloat162 a2 = *(const __nv_bfloat162*)(arow + d);
    float a0 = __bfloat162float(a2.x), a1 = __bfloat162float(a2.y);
    orow[t]           = __floats2bfloat162_rn(c0, c1);
    orow[t + 256]     = a2;
    orow[t + 512]     = __floats2bfloat162_rn(a0 - c0, a1 - c1);
    orow[t + 768]     = __floats2bfloat162_rn(a0 * c0, a1 * c1);
}

// ---------------------------------------------------------------------------
// Final fused dual GEMM on materialized cat: BM=128, BN=128, BK=32,
// 256 threads (8 warps = 4m x 2n, warp tile 32x64), 3-stage cp.async,
// dynamic smem (90KB). Epilogue: tanh/sigmoid/blend, gathered output rows.
// ---------------------------------------------------------------------------
__global__ __launch_bounds__(256, 1)
void final_mma2(const float* __restrict__ bfv, const float* __restrict__ bgv,
                float* __restrict__ out) {
    int b  = blockIdx.z;
    int m0 = blockIdx.y * 128;
    int n0 = blockIdx.x * 128;
    int M  = g_cnt[b];
    if (m0 >= M) return;

    extern __shared__ __align__(16) uint4 dyn[];
    uint4* sA  = dyn;              // [3][FCH]
    uint4* sBf = dyn + 3 * FCH;    // [3][FCH]
    uint4* sBg = dyn + 6 * FCH;    // [3][FCH]

    int tid = threadIdx.x;
    int ar = tid >> 1, ac = (tid & 1) * 2;   // A: 128 rows, 2 chunks/thread
    int br = tid >> 1, bc = (tid & 1) * 2;   // B: 128 rows, 2 chunks/thread/matrix

    int j = min(m0 + ar, M - 1);
    const bf16* Asrc  = g_catb + ((size_t)b * LC + j) * D4 + ac * 8;
    const bf16* Bfsrc = g_Wfb + (size_t)(n0 + br) * D4 + bc * 8;
    const bf16* Bgsrc = g_Wgb + (size_t)(n0 + br) * D4 + bc * 8;
    unsigned adst0  = sptr(sA)  + (unsigned)(ar * 5 + ac) * 16;
    unsigned bfdst0 = sptr(sBf) + (unsigned)(br * 5 + bc) * 16;
    unsigned bgdst0 = sptr(sBg) + (unsigned)(br * 5 + bc) * 16;

    int lane = tid & 31, w = tid >> 5;
    int wm = w >> 1, wn = w & 1;
    int a_off = (wm * 32 + (lane & 15)) * 5 + (lane >> 4);
    int b_off = (wn * 64 + ((lane >> 4) << 3) + (lane & 7)) * 5 + ((lane >> 3) & 1);

    float accf[2][8][4], accg[2][8][4];
#pragma unroll
    for (int mi = 0; mi < 2; mi++)
#pragma unroll
        for (int ni = 0; ni < 8; ni++)
#pragma unroll
            for (int r = 0; r < 4; r++) { accf[mi][ni][r] = 0.f; accg[mi][ni][r] = 0.f; }

    const int KIT = D4 / 32;   // 64

#define FISSUE(it_)                                                          \
    {                                                                        \
        int st_ = (it_) % 3;                                                 \
        unsigned so_ = (unsigned)st_ * (FCH * 16);                           \
        cpasync16(adst0 + so_,       Asrc + (it_) * 32);                     \
        cpasync16(adst0 + so_ + 16,  Asrc + (it_) * 32 + 8);                 \
        cpasync16(bfdst0 + so_,      Bfsrc + (it_) * 32);                    \
        cpasync16(bfdst0 + so_ + 16, Bfsrc + (it_) * 32 + 8);                \
        cpasync16(bgdst0 + so_,      Bgsrc + (it_) * 32);                    \
        cpasync16(bgdst0 + so_ + 16, Bgsrc + (it_) * 32 + 8);                \
    }

    FISSUE(0); cpcommit();
    FISSUE(1); cpcommit();

    for (int it = 0; it < KIT; it++) {
        cpwait<1>();
        __syncthreads();
        if (it + 2 < KIT) { FISSUE(it + 2); }
        cpcommit();
        int st = it % 3;
        unsigned abase  = sptr(sA)  + (unsigned)st * (FCH * 16);
        unsigned bfbase = sptr(sBf) + (unsigned)st * (FCH * 16);
        unsigned bgbase = sptr(sBg) + (unsigned)st * (FCH * 16);
#pragma unroll
        for (int ks = 0; ks < 2; ks++) {
            unsigned av[2][4], bvf[4][4], bvg[4][4];
#pragma unroll
            for (int mi = 0; mi < 2; mi++)
                ldsm4(av[mi], abase + (unsigned)(a_off + mi * 16 * 5 + ks * 2) * 16);
#pragma unroll
            for (int np = 0; np < 4; np++) {
                ldsm4(bvf[np], bfbase + (unsigned)(b_off + np * 16 * 5 + ks * 2) * 16);
                ldsm4(bvg[np], bgbase + (unsigned)(b_off + np * 16 * 5 + ks * 2) * 16);
            }
#pragma unroll
            for (int mi = 0; mi < 2; mi++)
#pragma unroll
                for (int ni = 0; ni < 8; ni++) {
                    unsigned bf2[2] = { bvf[ni >> 1][(ni & 1) * 2 + 0],
                                        bvf[ni >> 1][(ni & 1) * 2 + 1] };
                    unsigned bg2[2] = { bvg[ni >> 1][(ni & 1) * 2 + 0],
                                        bvg[ni >> 1][(ni & 1) * 2 + 1] };
                    mma_bf16(accf[mi][ni], av[mi], bf2);
                    mma_bf16(accg[mi][ni], av[mi], bg2);
                }
        }
    }
#undef FISSUE

    int gid = lane >> 2, tig = lane & 3;
#pragma unroll
    for (int mi = 0; mi < 2; mi++) {
#pragma unroll
        for (int rr = 0; rr < 2; rr++) {
            int jrow = m0 + wm * 32 + mi * 16 + gid + rr * 8;
            if (jrow < M) {
                int c = g_idx[b * LC + jrow];
                const bf16* catrow = g_catb + ((size_t)b * LC + jrow) * D4;
                float* orow = out + ((size_t)b * LC + c) * (size_t)D4;
#pragma unroll
                for (int ni = 0; ni < 8; ni++) {
                    int n = n0 + wn * 64 + ni * 8 + tig * 2;
                    __nv_bfloat162 cat2 = *(const __nv_bfloat162*)(catrow + n);
#pragma unroll
                    for (int e = 0; e < 2; e++) {
                        float catv = __bfloat162float(e ? cat2.y : cat2.x);
                        float df = accf[mi][ni][rr * 2 + e];
                        float dg = accg[mi][ni][rr * 2 + e];
                        float fv = tanhf(df + bfv[n + e]);
                        float gv = 1.0f / (1.0f + __expf(-(dg + bgv[n + e])));
                        orow[n + e] = gv * fv + (1.0f - gv) * catv;
                    }
                }
            }
        }
    }
}

// ---------------------------------------------------------------------------
extern "C" void kernel_launch(void* const* d_in, const int* in_sizes, int n_in,
                              void* d_out, int out_size) {
    const float* C     = (const float*)d_in[0];
    const float* Q     = (const float*)d_in[1];
    const int*   Cmask = (const int*)d_in[2];
    const int*   Qmask = (const int*)d_in[3];
    const float* W1    = (const float*)d_in[4];
    const float* b1    = (const float*)d_in[5];
    const float* Wf    = (const float*)d_in[6];
    const float* bfv   = (const float*)d_in[7];
    const float* Wg    = (const float*)d_in[8];
    const float* bgv   = (const float*)d_in[9];
    float* out = (float*)d_out;

    bf16* dCb;  cudaGetSymbolAddress((void**)&dCb,  g_Cb);
    bf16* dQb;  cudaGetSymbolAddress((void**)&dQb,  g_Qb);
    bf16* dQtb; cudaGetSymbolAddress((void**)&dQtb, g_Qtb);
    bf16* dW1b; cudaGetSymbolAddress((void**)&dW1b, g_W1b);
    bf16* dWfb; cudaGetSymbolAddress((void**)&dWfb, g_Wfb);
    bf16* dWgb; cudaGetSymbolAddress((void**)&dWgb, g_Wgb);
    bf16* dCpb; cudaGetSymbolAddress((void**)&dCpb, g_Cpb);
    bf16* dQpb; cudaGetSymbolAddress((void**)&dQpb, g_Qpb);
    float* dS;  cudaGetSymbolAddress((void**)&dS,   g_S);
    bf16* dSb;  cudaGetSymbolAddress((void**)&dSb,  g_Sb);
    bf16* dAb;  cudaGetSymbolAddress((void**)&dAb,  g_Ab);

    const int FINAL_SMEM = 9 * FCH * 16;   // 92160 B
    cudaFuncSetAttribute(final_mma2,
                         cudaFuncAttributeMaxDynamicSharedMemorySize, FINAL_SMEM);

    compact_kernel<<<NB, 256>>>(Cmask);
    fill_masked_kernel<<<dim3(1, LC, NB), 128>>>(Cmask, out);

    // one-time fp32 -> bf16 conversions
    cvt_kernel<<<(NB * LC * DD / 8 + 255) / 256, 256>>>(C,  dCb,  NB * LC * DD / 8);
    cvt_kernel<<<(NB * LQ * DD / 8 + 255) / 256, 256>>>(Q,  dQb,  NB * LQ * DD / 8);
    cvt_kernel<<<(DD * DD / 8 + 255) / 256, 256>>>(W1, dW1b, DD * DD / 8);
    cvt_kernel<<<(D4 * D4 / 8 + 255) / 256, 256>>>(Wf, dWfb, D4 * D4 / 8);
    cvt_kernel<<<(D4 * D4 / 8 + 255) / 256, 256>>>(Wg, dWgb, D4 * D4 / 8);
    transpose_q_kernel<<<dim3(DD / 32, LQ / 32, NB), dim3(32, 8)>>>(Q);

    // C_ = lrelu(C@W1^T + b1), compacted rows
    gemm_bf16<<<dim3(DD / 64, LC / 128, NB), 256>>>(
        dCb, DD, LC, dW1b, DD, 0, dCpb, DD, b1, DD, LC, 1, 1, 0);
    // Q_ = lrelu(Q@W1^T + b1), all rows
    gemm_bf16<<<dim3(DD / 64, LQ / 128, NB), 256>>>(
        dQb, DD, LQ, dW1b, DD, 0, dQpb, DD, b1, DD, LQ, 0, 0, 0);
    // S = C_ @ Q_^T (compacted c; batched B) -> fp32
    gemm_bf16<<<dim3(LQ / 64, LC / 128, NB), 256>>>(
        dCpb, DD, LC, dQpb, DD, LQ, dS, LQ, b1, DD, LC, 1, 0, 1);
    // masked softmax -> bf16 probabilities
    softmax_kernel<<<dim3(LC, NB), 256>>>(Qmask);
    // attn_C = S_ @ Qt^T (compacted c; batched B) -> bf16
    gemm_bf16<<<dim3(DD / 64, LC / 128, NB), 256>>>(
        dSb, LQ, LC, dQtb, LQ, DD, dAb, DD, b1, LQ, LC, 1, 0, 2);
    // materialize cat, then fused dual GEMM + blend epilogue
    cat_kernel<<<dim3(LC, NB), 256>>>(C);
    final_mma2<<<dim3(D4 / 128, LC / 128, NB), 256, FINAL_SMEM>>>(bfv, bgv, out);
}

// round 9
// speedup vs baseline: 3.5978x; 1.1329x over previous
#include <cuda_runtime.h>
#include <cuda_bf16.h>
#include <math.h>

#define NEG_INF (-1e30f)
#define NB 16
#define LC 2048
#define LQ 512
#define DD 512
#define D4 2048

typedef __nv_bfloat16 bf16;

// bf16 scratch (converted once per launch)
__device__ bf16  g_Cb [NB * LC * DD];
__device__ bf16  g_Qb [NB * LQ * DD];
__device__ bf16  g_Qtb[NB * DD * LQ];
__device__ bf16  g_W1b[DD * DD];
__device__ bf16  g_Wfb[D4 * D4];
__device__ bf16  g_Wgb[D4 * D4];
__device__ bf16  g_Cpb[NB * LC * DD];
__device__ bf16  g_Qpb[NB * LQ * DD];
__device__ float g_S  [NB * LC * LQ];
__device__ bf16  g_Sb [NB * LC * LQ];
__device__ bf16  g_Ab [NB * LC * DD];
__device__ bf16  g_catb[(size_t)NB * LC * D4];   // materialized cat (compacted rows)
__device__ int   g_idx[NB * LC];
__device__ int   g_cnt[NB];

// ---------------------------------------------------------------------------
__device__ __forceinline__ unsigned pk(float a, float b) {
    __nv_bfloat162 h = __floats2bfloat162_rn(a, b);
    return *reinterpret_cast<unsigned*>(&h);
}

__device__ __forceinline__ void mma_bf16(float* d, const unsigned* a, const unsigned* b) {
    asm volatile(
        "mma.sync.aligned.m16n8k16.row.col.f32.bf16.bf16.f32 "
        "{%0,%1,%2,%3}, {%4,%5,%6,%7}, {%8,%9}, {%0,%1,%2,%3};\n"
        : "+f"(d[0]), "+f"(d[1]), "+f"(d[2]), "+f"(d[3])
        : "r"(a[0]), "r"(a[1]), "r"(a[2]), "r"(a[3]), "r"(b[0]), "r"(b[1]));
}

__device__ __forceinline__ void ldsm4(unsigned* r, unsigned addr) {
    asm volatile("ldmatrix.sync.aligned.m8n8.x4.shared.b16 {%0,%1,%2,%3}, [%4];"
                 : "=r"(r[0]), "=r"(r[1]), "=r"(r[2]), "=r"(r[3]) : "r"(addr));
}

__device__ __forceinline__ unsigned sptr(const void* p) {
    return (unsigned)__cvta_generic_to_shared(p);
}

__device__ __forceinline__ void cpasync16(unsigned dst, const void* src) {
    asm volatile("cp.async.cg.shared.global [%0], [%1], 16;\n" :: "r"(dst), "l"(src));
}
__device__ __forceinline__ void cpcommit() {
    asm volatile("cp.async.commit_group;\n" ::: "memory");
}
template <int N> __device__ __forceinline__ void cpwait() {
    asm volatile("cp.async.wait_group %0;\n" :: "n"(N) : "memory");
}

// SMEM: row-major bf16 tiles, row stride = 5 x 16B chunks (80B).
// (5r + c) mod 8 permutes bank-groups -> ldmatrix conflict-free, no swizzle.
#define ACH (128 * 5)
#define BCH (64 * 5)
#define FCH (128 * 5)   // final kernel tiles: 128 rows

// ---------------------------------------------------------------------------
__global__ void compact_kernel(const int* __restrict__ Cmask) {
    __shared__ int toff[257];
    int b = blockIdx.x;
    int t = threadIdx.x;
    int flags[8];
    int s = 0;
#pragma unroll
    for (int i = 0; i < 8; i++) {
        flags[i] = (Cmask[b * LC + t * 8 + i] != 0) ? 1 : 0;
        s += flags[i];
    }
    toff[t + 1] = s;
    __syncthreads();
    if (t == 0) {
        toff[0] = 0;
        for (int i = 1; i <= 256; i++) toff[i] += toff[i - 1];
        g_cnt[b] = toff[256];
    }
    __syncthreads();
    int pos = toff[t];
#pragma unroll
    for (int i = 0; i < 8; i++) {
        if (flags[i]) g_idx[b * LC + (pos++)] = t * 8 + i;
    }
}

__global__ void fill_masked_kernel(const int* __restrict__ Cmask,
                                   float* __restrict__ out) {
    int c = blockIdx.y;
    int b = blockIdx.z;
    if (Cmask[b * LC + c] != 0) return;
    float4* p = (float4*)(out + ((size_t)(b * LC + c)) * D4);
    float4 v = make_float4(NEG_INF, NEG_INF, NEG_INF, NEG_INF);
    int t = threadIdx.x;
    p[t] = v; p[t + 128] = v; p[t + 256] = v; p[t + 384] = v;
}

// fp32 -> bf16 bulk convert (8 elems / thread)
__global__ void cvt_kernel(const float* __restrict__ src, bf16* __restrict__ dst,
                           int n8) {
    int i = blockIdx.x * blockDim.x + threadIdx.x;
    if (i >= n8) return;
    const float4* s = (const float4*)src + (size_t)i * 2;
    float4 a = s[0], b = s[1];
    uint4 o;
    o.x = pk(a.x, a.y); o.y = pk(a.z, a.w);
    o.z = pk(b.x, b.y); o.w = pk(b.z, b.w);
    ((uint4*)dst)[i] = o;
}

// Q fp32 -> transposed bf16: g_Qtb[b][d][q]
__global__ void transpose_q_kernel(const float* __restrict__ Q) {
    __shared__ float t[32][33];
    int b = blockIdx.z;
    int d0 = blockIdx.x * 32, q0 = blockIdx.y * 32;
    int tx = threadIdx.x, ty = threadIdx.y;
#pragma unroll
    for (int i = 0; i < 4; i++)
        t[ty + i * 8][tx] = Q[((size_t)b * LQ + q0 + ty + i * 8) * DD + d0 + tx];
    __syncthreads();
#pragma unroll
    for (int i = 0; i < 4; i++)
        g_Qtb[((size_t)b * DD + d0 + ty + i * 8) * LQ + q0 + tx] =
            __float2bfloat16(t[tx][ty + i * 8]);
}

// ---------------------------------------------------------------------------
// Generic bf16 NT GEMM: 3-stage cp.async pipeline, ldmatrix consumer.
// BM=128 BN=64 BK=32, 256 threads (8 warps = 4m x 2n of 32x32).
// mode 0: bias + leaky_relu -> bf16; mode 1: fp32 out; mode 2: bf16 out.
// ---------------------------------------------------------------------------
__global__ __launch_bounds__(256, 2)
void gemm_bf16(const bf16* __restrict__ A, int lda, int Arows_per_b,
               const bf16* __restrict__ B, int ldb, int Brows_per_b,
               void* __restrict__ Yv, int ldy,
               const float* __restrict__ bias,
               int K, int Mfull, int use_cnt, int gather, int mode) {
    int b  = blockIdx.z;
    int m0 = blockIdx.y * 128;
    int n0 = blockIdx.x * 64;
    int M  = use_cnt ? g_cnt[b] : Mfull;
    if (m0 >= M) return;

    __shared__ __align__(16) uint4 sA[3][ACH];
    __shared__ __align__(16) uint4 sB[3][BCH];

    int tid = threadIdx.x;
    int ar = tid >> 1, ac = (tid & 1) * 2;
    int br = tid >> 2, bc = tid & 3;
    int j = min(m0 + ar, M - 1);
    int srow = gather ? g_idx[b * LC + j] : j;
    const bf16* Asrc = A + ((size_t)b * Arows_per_b + srow) * lda + ac * 8;
    const bf16* Bsrc = B + ((size_t)b * Brows_per_b + n0 + br) * ldb + bc * 8;
    unsigned adst0 = sptr(&sA[0][0]) + (unsigned)(ar * 5 + ac) * 16;
    unsigned bdst0 = sptr(&sB[0][0]) + (unsigned)(br * 5 + bc) * 16;

    int lane = tid & 31, w = tid >> 5;
    int wm = w >> 1, wn = w & 1;
    int a_off = (wm * 32 + (lane & 15)) * 5 + (lane >> 4);
    int b_off = (wn * 32 + ((lane >> 4) << 3) + (lane & 7)) * 5 + ((lane >> 3) & 1);

    float acc[2][4][4];
#pragma unroll
    for (int mi = 0; mi < 2; mi++)
#pragma unroll
        for (int ni = 0; ni < 4; ni++)
#pragma unroll
            for (int r = 0; r < 4; r++) acc[mi][ni][r] = 0.f;

    const int KIT = K / 32;

#define ISSUE(it_)                                                          \
    {                                                                       \
        int st_ = (it_) % 3;                                                \
        cpasync16(adst0 + (unsigned)st_ * (ACH * 16), Asrc + (it_) * 32);   \
        cpasync16(adst0 + (unsigned)st_ * (ACH * 16) + 16,                  \
                  Asrc + (it_) * 32 + 8);                                   \
        cpasync16(bdst0 + (unsigned)st_ * (BCH * 16), Bsrc + (it_) * 32);   \
    }

    ISSUE(0); cpcommit();
    if (KIT > 1) { ISSUE(1); } cpcommit();

    for (int it = 0; it < KIT; it++) {
        cpwait<1>();
        __syncthreads();
        if (it + 2 < KIT) { ISSUE(it + 2); }
        cpcommit();
        int st = it % 3;
        unsigned abase = sptr(&sA[st][0]);
        unsigned bbase = sptr(&sB[st][0]);
#pragma unroll
        for (int ks = 0; ks < 2; ks++) {
            unsigned av[2][4], bv[2][4];
#pragma unroll
            for (int mi = 0; mi < 2; mi++)
                ldsm4(av[mi], abase + (unsigned)(a_off + mi * 16 * 5 + ks * 2) * 16);
#pragma unroll
            for (int np = 0; np < 2; np++)
                ldsm4(bv[np], bbase + (unsigned)(b_off + np * 16 * 5 + ks * 2) * 16);
#pragma unroll
            for (int mi = 0; mi < 2; mi++)
#pragma unroll
                for (int ni = 0; ni < 4; ni++) {
                    unsigned bb[2] = { bv[ni >> 1][(ni & 1) * 2 + 0],
                                       bv[ni >> 1][(ni & 1) * 2 + 1] };
                    mma_bf16(acc[mi][ni], av[mi], bb);
                }
        }
    }
#undef ISSUE

    int gid = lane >> 2, tig = lane & 3;
#pragma unroll
    for (int mi = 0; mi < 2; mi++) {
#pragma unroll
        for (int rr = 0; rr < 2; rr++) {
            int m = m0 + wm * 32 + mi * 16 + gid + rr * 8;
            if (m >= M) continue;
            if (mode == 1) {
                float* yr = (float*)Yv + ((size_t)b * Arows_per_b + m) * ldy;
#pragma unroll
                for (int ni = 0; ni < 4; ni++) {
                    int n = n0 + wn * 32 + ni * 8 + tig * 2;
                    yr[n]     = acc[mi][ni][rr * 2 + 0];
                    yr[n + 1] = acc[mi][ni][rr * 2 + 1];
                }
            } else {
                bf16* yr = (bf16*)Yv + ((size_t)b * Arows_per_b + m) * ldy;
#pragma unroll
                for (int ni = 0; ni < 4; ni++) {
                    int n = n0 + wn * 32 + ni * 8 + tig * 2;
                    float v0 = acc[mi][ni][rr * 2 + 0];
                    float v1 = acc[mi][ni][rr * 2 + 1];
                    if (mode == 0) {
                        v0 += bias[n];     v1 += bias[n + 1];
                        v0 = (v0 > 0.f) ? v0 : 0.01f * v0;
                        v1 = (v1 > 0.f) ? v1 : 0.01f * v1;
                    }
                    *(__nv_bfloat162*)(yr + n) = __floats2bfloat162_rn(v0, v1);
                }
            }
        }
    }
}

// ---------------------------------------------------------------------------
// Softmax over q with Qmask: reads fp32 g_S, writes bf16 g_Sb.
// ---------------------------------------------------------------------------
__global__ void softmax_kernel(const int* __restrict__ Qmask) {
    int b = blockIdx.y, j = blockIdx.x;
    if (j >= g_cnt[b]) return;
    const float* row = g_S + ((size_t)b * LC + j) * LQ;
    bf16* orow = g_Sb + ((size_t)b * LC + j) * LQ;
    int t = threadIdx.x;
    int lane = t & 31, warp = t >> 5;
    float v0 = row[t];
    float v1 = row[t + 256];
    if (Qmask[b * LQ + t] == 0) v0 = NEG_INF;
    if (Qmask[b * LQ + t + 256] == 0) v1 = NEG_INF;

    __shared__ float red[8];
    __shared__ float bcast;

    float m = fmaxf(v0, v1);
#pragma unroll
    for (int o = 16; o; o >>= 1) m = fmaxf(m, __shfl_xor_sync(0xffffffffu, m, o));
    if (lane == 0) red[warp] = m;
    __syncthreads();
    if (t < 32) {
        float x = (t < 8) ? red[t] : -3.4e38f;
#pragma unroll
        for (int o = 4; o; o >>= 1) x = fmaxf(x, __shfl_xor_sync(0xffffffffu, x, o));
        if (t == 0) bcast = x;
    }
    __syncthreads();
    m = bcast;
    float e0 = expf(v0 - m), e1 = expf(v1 - m);
    float sum = e0 + e1;
#pragma unroll
    for (int o = 16; o; o >>= 1) sum += __shfl_xor_sync(0xffffffffu, sum, o);
    __syncthreads();
    if (lane == 0) red[warp] = sum;
    __syncthreads();
    if (t < 32) {
        float x = (t < 8) ? red[t] : 0.f;
#pragma unroll
        for (int o = 4; o; o >>= 1) x += __shfl_xor_sync(0xffffffffu, x, o);
        if (t == 0) bcast = x;
    }
    __syncthreads();
    float inv = 1.0f / bcast;
    orow[t]       = __float2bfloat16(e0 * inv);
    orow[t + 256] = __float2bfloat16(e1 * inv);
}

// ---------------------------------------------------------------------------
// Materialize cat = [C | A | A-C | A*C] as bf16, compacted rows.
// ---------------------------------------------------------------------------
__global__ void cat_kernel(const float* __restrict__ C) {
    int b = blockIdx.y, j = blockIdx.x;
    if (j >= g_cnt[b]) return;
    int c = g_idx[b * LC + j];
    const float* crow = C + ((size_t)b * LC + c) * DD;
    const bf16* arow = g_Ab + ((size_t)b * LC + j) * DD;
    __nv_bfloat162* orow = (__nv_bfloat162*)(g_catb + ((size_t)b * LC + j) * D4);
    int t = threadIdx.x;   // 256 threads, 2 elems each
    int d = t * 2;
    float c0 = crow[d], c1 = crow[d + 1];
    __nv_bfloat162 a2 = *(const __nv_bfloat162*)(arow + d);
    float a0 = __bfloat162float(a2.x), a1 = __bfloat162float(a2.y);
    orow[t]           = __floats2bfloat162_rn(c0, c1);
    orow[t + 256]     = a2;
    orow[t + 512]     = __floats2bfloat162_rn(a0 - c0, a1 - c1);
    orow[t + 768]     = __floats2bfloat162_rn(a0 * c0, a1 * c1);
}

// ---------------------------------------------------------------------------
// Final fused dual GEMM on materialized cat: BM=128, BN=128, BK=32,
// 512 threads (16 warps = 4m x 4n, warp tile 32x32), 3-stage cp.async,
// dynamic smem (90KB). Epilogue: tanh/sigmoid/blend, gathered output rows.
// ---------------------------------------------------------------------------
__global__ __launch_bounds__(512, 1)
void final_mma3(const float* __restrict__ bfv, const float* __restrict__ bgv,
                float* __restrict__ out) {
    int b  = blockIdx.z;
    int m0 = blockIdx.y * 128;
    int n0 = blockIdx.x * 128;
    int M  = g_cnt[b];
    if (m0 >= M) return;

    extern __shared__ __align__(16) uint4 dyn[];
    uint4* sA  = dyn;              // [3][FCH]
    uint4* sBf = dyn + 3 * FCH;    // [3][FCH]
    uint4* sBg = dyn + 6 * FCH;    // [3][FCH]

    int tid = threadIdx.x;
    int ar = tid >> 2, ac = tid & 3;   // 128 rows x 4 chunks, 1 chunk/thread

    int j = min(m0 + ar, M - 1);
    const bf16* Asrc  = g_catb + ((size_t)b * LC + j) * D4 + ac * 8;
    const bf16* Bfsrc = g_Wfb + (size_t)(n0 + ar) * D4 + ac * 8;
    const bf16* Bgsrc = g_Wgb + (size_t)(n0 + ar) * D4 + ac * 8;
    unsigned dst0 = (unsigned)(ar * 5 + ac) * 16;
    unsigned adst0  = sptr(sA)  + dst0;
    unsigned bfdst0 = sptr(sBf) + dst0;
    unsigned bgdst0 = sptr(sBg) + dst0;

    int lane = tid & 31, w = tid >> 5;
    int wm = w >> 2, wn = w & 3;
    int a_off = (wm * 32 + (lane & 15)) * 5 + (lane >> 4);
    int b_off = (wn * 32 + ((lane >> 4) << 3) + (lane & 7)) * 5 + ((lane >> 3) & 1);

    float accf[2][4][4], accg[2][4][4];
#pragma unroll
    for (int mi = 0; mi < 2; mi++)
#pragma unroll
        for (int ni = 0; ni < 4; ni++)
#pragma unroll
            for (int r = 0; r < 4; r++) { accf[mi][ni][r] = 0.f; accg[mi][ni][r] = 0.f; }

    const int KIT = D4 / 32;   // 64

#define FISSUE(it_)                                                          \
    {                                                                        \
        int st_ = (it_) % 3;                                                 \
        unsigned so_ = (unsigned)st_ * (FCH * 16);                           \
        cpasync16(adst0 + so_,  Asrc + (it_) * 32);                          \
        cpasync16(bfdst0 + so_, Bfsrc + (it_) * 32);                         \
        cpasync16(bgdst0 + so_, Bgsrc + (it_) * 32);                         \
    }

    FISSUE(0); cpcommit();
    FISSUE(1); cpcommit();

    for (int it = 0; it < KIT; it++) {
        cpwait<1>();
        __syncthreads();
        if (it + 2 < KIT) { FISSUE(it + 2); }
        cpcommit();
        int st = it % 3;
        unsigned abase  = sptr(sA)  + (unsigned)st * (FCH * 16);
        unsigned bfbase = sptr(sBf) + (unsigned)st * (FCH * 16);
        unsigned bgbase = sptr(sBg) + (unsigned)st * (FCH * 16);
#pragma unroll
        for (int ks = 0; ks < 2; ks++) {
            unsigned av[2][4], bvf[2][4], bvg[2][4];
#pragma unroll
            for (int mi = 0; mi < 2; mi++)
                ldsm4(av[mi], abase + (unsigned)(a_off + mi * 16 * 5 + ks * 2) * 16);
#pragma unroll
            for (int np = 0; np < 2; np++) {
                ldsm4(bvf[np], bfbase + (unsigned)(b_off + np * 16 * 5 + ks * 2) * 16);
                ldsm4(bvg[np], bgbase + (unsigned)(b_off + np * 16 * 5 + ks * 2) * 16);
            }
#pragma unroll
            for (int mi = 0; mi < 2; mi++)
#pragma unroll
                for (int ni = 0; ni < 4; ni++) {
                    unsigned bf2[2] = { bvf[ni >> 1][(ni & 1) * 2 + 0],
                                        bvf[ni >> 1][(ni & 1) * 2 + 1] };
                    unsigned bg2[2] = { bvg[ni >> 1][(ni & 1) * 2 + 0],
                                        bvg[ni >> 1][(ni & 1) * 2 + 1] };
                    mma_bf16(accf[mi][ni], av[mi], bf2);
                    mma_bf16(accg[mi][ni], av[mi], bg2);
                }
        }
    }
#undef FISSUE

    int gid = lane >> 2, tig = lane & 3;
#pragma unroll
    for (int mi = 0; mi < 2; mi++) {
#pragma unroll
        for (int rr = 0; rr < 2; rr++) {
            int jrow = m0 + wm * 32 + mi * 16 + gid + rr * 8;
            if (jrow < M) {
                int c = g_idx[b * LC + jrow];
                const bf16* catrow = g_catb + ((size_t)b * LC + jrow) * D4;
                float* orow = out + ((size_t)b * LC + c) * (size_t)D4;
#pragma unroll
                for (int ni = 0; ni < 4; ni++) {
                    int n = n0 + wn * 32 + ni * 8 + tig * 2;
                    __nv_bfloat162 cat2 = *(const __nv_bfloat162*)(catrow + n);
#pragma unroll
                    for (int e = 0; e < 2; e++) {
                        float catv = __bfloat162float(e ? cat2.y : cat2.x);
                        float df = accf[mi][ni][rr * 2 + e];
                        float dg = accg[mi][ni][rr * 2 + e];
                        float fv = tanhf(df + bfv[n + e]);
                        float gv = 1.0f / (1.0f + __expf(-(dg + bgv[n + e])));
                        orow[n + e] = gv * fv + (1.0f - gv) * catv;
                    }
                }
            }
        }
    }
}

// ---------------------------------------------------------------------------
extern "C" void kernel_launch(void* const* d_in, const int* in_sizes, int n_in,
                              void* d_out, int out_size) {
    const float* C     = (const float*)d_in[0];
    const float* Q     = (const float*)d_in[1];
    const int*   Cmask = (const int*)d_in[2];
    const int*   Qmask = (const int*)d_in[3];
    const float* W1    = (const float*)d_in[4];
    const float* b1    = (const float*)d_in[5];
    const float* Wf    = (const float*)d_in[6];
    const float* bfv   = (const float*)d_in[7];
    const float* Wg    = (const float*)d_in[8];
    const float* bgv   = (const float*)d_in[9];
    float* out = (float*)d_out;

    bf16* dCb;  cudaGetSymbolAddress((void**)&dCb,  g_Cb);
    bf16* dQb;  cudaGetSymbolAddress((void**)&dQb,  g_Qb);
    bf16* dQtb; cudaGetSymbolAddress((void**)&dQtb, g_Qtb);
    bf16* dW1b; cudaGetSymbolAddress((void**)&dW1b, g_W1b);
    bf16* dWfb; cudaGetSymbolAddress((void**)&dWfb, g_Wfb);
    bf16* dWgb; cudaGetSymbolAddress((void**)&dWgb, g_Wgb);
    bf16* dCpb; cudaGetSymbolAddress((void**)&dCpb, g_Cpb);
    bf16* dQpb; cudaGetSymbolAddress((void**)&dQpb, g_Qpb);
    float* dS;  cudaGetSymbolAddress((void**)&dS,   g_S);
    bf16* dSb;  cudaGetSymbolAddress((void**)&dSb,  g_Sb);
    bf16* dAb;  cudaGetSymbolAddress((void**)&dAb,  g_Ab);

    const int FINAL_SMEM = 9 * FCH * 16;   // 92160 B
    cudaFuncSetAttribute(final_mma3,
                         cudaFuncAttributeMaxDynamicSharedMemorySize, FINAL_SMEM);

    compact_kernel<<<NB, 256>>>(Cmask);
    fill_masked_kernel<<<dim3(1, LC, NB), 128>>>(Cmask, out);

    // one-time fp32 -> bf16 conversions
    cvt_kernel<<<(NB * LC * DD / 8 + 255) / 256, 256>>>(C,  dCb,  NB * LC * DD / 8);
    cvt_kernel<<<(NB * LQ * DD / 8 + 255) / 256, 256>>>(Q,  dQb,  NB * LQ * DD / 8);
    cvt_kernel<<<(DD * DD / 8 + 255) / 256, 256>>>(W1, dW1b, DD * DD / 8);
    cvt_kernel<<<(D4 * D4 / 8 + 255) / 256, 256>>>(Wf, dWfb, D4 * D4 / 8);
    cvt_kernel<<<(D4 * D4 / 8 + 255) / 256, 256>>>(Wg, dWgb, D4 * D4 / 8);
    transpose_q_kernel<<<dim3(DD / 32, LQ / 32, NB), dim3(32, 8)>>>(Q);

    // C_ = lrelu(C@W1^T + b1), compacted rows
    gemm_bf16<<<dim3(DD / 64, LC / 128, NB), 256>>>(
        dCb, DD, LC, dW1b, DD, 0, dCpb, DD, b1, DD, LC, 1, 1, 0);
    // Q_ = lrelu(Q@W1^T + b1), all rows
    gemm_bf16<<<dim3(DD / 64, LQ / 128, NB), 256>>>(
        dQb, DD, LQ, dW1b, DD, 0, dQpb, DD, b1, DD, LQ, 0, 0, 0);
    // S = C_ @ Q_^T (compacted c; batched B) -> fp32
    gemm_bf16<<<dim3(LQ / 64, LC / 128, NB), 256>>>(
        dCpb, DD, LC, dQpb, DD, LQ, dS, LQ, b1, DD, LC, 1, 0, 1);
    // masked softmax -> bf16 probabilities
    softmax_kernel<<<dim3(LC, NB), 256>>>(Qmask);
    // attn_C = S_ @ Qt^T (compacted c; batched B) -> bf16
    gemm_bf16<<<dim3(DD / 64, LC / 128, NB), 256>>>(
        dSb, LQ, LC, dQtb, LQ, DD, dAb, DD, b1, LQ, LC, 1, 0, 2);
    // materialize cat, then fused dual GEMM + blend epilogue
    cat_kernel<<<dim3(LC, NB), 256>>>(C);
    final_mma3<<<dim3(D4 / 128, LC / 128, NB), 512, FINAL_SMEM>>>(bfv, bgv, out);
}